// round 5
// baseline (speedup 1.0000x reference)
#include <cuda_runtime.h>
#include <math.h>

// Problem dims (fixed by dataset): B=1024, I=512, O=512.
#define I_DIM 512
#define O_DIM 512

#define BM 64
#define BN 64
#define BK 16

// Scratch (allocation-free: __device__ globals)
__device__ __align__(16) float g_s2 [O_DIM * I_DIM];   // inv_covar^2 + 1e-32
__device__ __align__(16) float g_cs2[O_DIM * I_DIM];   // centers * s2
__device__ __align__(16) float g_K  [O_DIM];           // sum_i c^2 * s2

typedef unsigned long long u64;

// Packed dual-FMA: d.f32x2 += a.f32x2 * b.f32x2  (sm_100+; ptxas never emits
// this from C++ — only reachable via PTX. 2 FMAs per issue slot & pipe slot.)
__device__ __forceinline__ void ffma2(u64 &d, u64 a, u64 b) {
    asm("fma.rn.f32x2 %0, %1, %2, %0;" : "+l"(d) : "l"(a), "l"(b));
}

// ---------------------------------------------------------------------------
// Prep: s2 = v^2 + eps, cs2 = c*s2, K[o] = sum c^2 s2.
// ---------------------------------------------------------------------------
__global__ void fgn_prep_kernel(const float* __restrict__ centers,
                                const float* __restrict__ inv_covars)
{
    int o = blockIdx.x;
    int t = threadIdx.x;
    __shared__ float red[256];

    float ksum = 0.0f;
    for (int i = t; i < I_DIM; i += 256) {
        float v  = inv_covars[o * I_DIM + i];
        float c  = centers   [o * I_DIM + i];
        float s2 = v * v + 1e-32f;
        float cs = c * s2;
        g_s2 [o * I_DIM + i] = s2;
        g_cs2[o * I_DIM + i] = cs;
        ksum += c * cs;
    }
    red[t] = ksum;
    __syncthreads();
    #pragma unroll
    for (int s = 128; s > 0; s >>= 1) {
        if (t < s) red[t] += red[t + s];
        __syncthreads();
    }
    if (t == 0) g_K[o] = red[0];
}

// ---------------------------------------------------------------------------
// Fused triple-GEMM via packed f32x2 FMAs.
//   accL = X @ W^T, accA = X^2 @ s2^T, accB = X @ (c*s2)^T
//   out  = (accL + bias) * exp(-(accA - 2*accB + K))
//
// Smem layout (k-major):
//   Xd [k][2m]  = {x_m, x_m}      duplicated pairs (a-operand broadcast)
//   X2d[k][2m]  = {x_m^2, x_m^2}  (squared at staging — off the FMA pipe)
//   Wt/St/Ct[k][n]                natural; contiguous n gives f32x2 pairs
//
// Per thread (4m x 4n = 4m x 2 n-pairs): per k-step
//   7 LDS.128 + 24 FFMA2  -> 31 issue slots vs 48 FFMA2-pipe cycles
//   => FFMA2-pipe-bound with 2 warps/SMSP.
// ---------------------------------------------------------------------------
__global__ __launch_bounds__(256, 1)
void fgn_main_kernel(const float* __restrict__ X,
                     const float* __restrict__ W,
                     const float* __restrict__ bias,
                     float* __restrict__ out)
{
    __shared__ float Xd [BK][2 * BM];   // 8 KB
    __shared__ float X2d[BK][2 * BM];   // 8 KB
    __shared__ float Wt [BK][BN];       // 4 KB
    __shared__ float St [BK][BN];       // 4 KB
    __shared__ float Ct [BK][BN];       // 4 KB   (28 KB total)

    const int tid = threadIdx.x;
    const int tx  = tid & 15;           // n fragment lane: n = 4*tx + {0..3}
    const int ty  = tid >> 4;           // m fragment lane: m = 4*ty + {0..3}
    const int m0  = blockIdx.y * BM;
    const int n0  = blockIdx.x * BN;

    // Staging mapping: 64 rows x 16 k = 1024 floats per tile = 256 float4.
    const int row = tid & 63;
    const int q   = (tid >> 6) << 2;    // k-offset within tile (0,4,8,12)

    const float4* gX = (const float4*)&X    [(size_t)(m0 + row) * I_DIM + q];
    const float4* gW = (const float4*)&W    [(size_t)(n0 + row) * I_DIM + q];
    const float4* gS = (const float4*)&g_s2 [(size_t)(n0 + row) * I_DIM + q];
    const float4* gC = (const float4*)&g_cs2[(size_t)(n0 + row) * I_DIM + q];

    u64 accL[4][2] = {};   // [m][n-pair], each u64 = {n_even, n_odd}
    u64 accA[4][2] = {};
    u64 accB[4][2] = {};

    auto sts_all = [&](float4 xv, float4 wv, float4 sv, float4 cv) {
        float xs[4] = {xv.x, xv.y, xv.z, xv.w};
        float ws[4] = {wv.x, wv.y, wv.z, wv.w};
        float ss[4] = {sv.x, sv.y, sv.z, sv.w};
        float cs[4] = {cv.x, cv.y, cv.z, cv.w};
        #pragma unroll
        for (int j = 0; j < 4; j++) {
            // dup-pair stores: 32 lanes x 8B contiguous => conflict-free
            *(float2*)&Xd [q + j][2 * row] = make_float2(xs[j], xs[j]);
            float x2 = xs[j] * xs[j];
            *(float2*)&X2d[q + j][2 * row] = make_float2(x2, x2);
            Wt[q + j][row] = ws[j];     // bank = row&31 => conflict-free
            St[q + j][row] = ss[j];
            Ct[q + j][row] = cs[j];
        }
    };

    auto compute = [&]() {
        #pragma unroll
        for (int k = 0; k < BK; k++) {
            // a-operands: duplicated pairs, one LDS.128 = 2 m-values
            ulonglong2 xa  = *(const ulonglong2*)&Xd [k][8 * ty];
            ulonglong2 xb  = *(const ulonglong2*)&Xd [k][8 * ty + 4];
            ulonglong2 x2a = *(const ulonglong2*)&X2d[k][8 * ty];
            ulonglong2 x2b = *(const ulonglong2*)&X2d[k][8 * ty + 4];
            // b-operands: natural pairs, one LDS.128 = 2 n-pairs
            ulonglong2 wv  = *(const ulonglong2*)&Wt[k][4 * tx];
            ulonglong2 sv  = *(const ulonglong2*)&St[k][4 * tx];
            ulonglong2 cv  = *(const ulonglong2*)&Ct[k][4 * tx];

            u64 xm [4] = {xa.x,  xa.y,  xb.x,  xb.y };
            u64 x2m[4] = {x2a.x, x2a.y, x2b.x, x2b.y};
            u64 wp [2] = {wv.x, wv.y};
            u64 sp [2] = {sv.x, sv.y};
            u64 cp [2] = {cv.x, cv.y};

            #pragma unroll
            for (int mi = 0; mi < 4; mi++) {
                #pragma unroll
                for (int p = 0; p < 2; p++) {
                    ffma2(accL[mi][p], xm [mi], wp[p]);
                    ffma2(accA[mi][p], x2m[mi], sp[p]);
                    ffma2(accB[mi][p], xm [mi], cp[p]);
                }
            }
        }
    };

    // Prologue: stage tile 0
    sts_all(gX[0], gW[0], gS[0], gC[0]);
    __syncthreads();

    // Main loop with register prefetch (hide LDG latency behind compute)
    #pragma unroll 1
    for (int it = 1; it < I_DIM / BK; it++) {
        float4 nx = gX[it * 4];
        float4 nw = gW[it * 4];
        float4 ns = gS[it * 4];
        float4 nc = gC[it * 4];
        compute();
        __syncthreads();
        sts_all(nx, nw, ns, nc);
        __syncthreads();
    }
    compute();

    // Epilogue: out = (L + bias) * exp(-(A - 2B + K)); vector STG.128
    const float4 bv = *(const float4*)&bias[n0 + 4 * tx];
    const float4 kv = *(const float4*)&g_K [n0 + 4 * tx];
    float bb[4] = {bv.x, bv.y, bv.z, bv.w};
    float kk[4] = {kv.x, kv.y, kv.z, kv.w};

    #pragma unroll
    for (int mi = 0; mi < 4; mi++) {
        int m = m0 + 4 * ty + mi;
        float o4[4];
        #pragma unroll
        for (int p = 0; p < 2; p++) {
            float L0 = __uint_as_float((unsigned)(accL[mi][p] & 0xffffffffu));
            float L1 = __uint_as_float((unsigned)(accL[mi][p] >> 32));
            float A0 = __uint_as_float((unsigned)(accA[mi][p] & 0xffffffffu));
            float A1 = __uint_as_float((unsigned)(accA[mi][p] >> 32));
            float B0 = __uint_as_float((unsigned)(accB[mi][p] & 0xffffffffu));
            float B1 = __uint_as_float((unsigned)(accB[mi][p] >> 32));
            float g0 = A0 - 2.0f * B0 + kk[2 * p + 0];
            float g1 = A1 - 2.0f * B1 + kk[2 * p + 1];
            o4[2 * p + 0] = (L0 + bb[2 * p + 0]) * expf(-g0);
            o4[2 * p + 1] = (L1 + bb[2 * p + 1]) * expf(-g1);
        }
        *(float4*)&out[(size_t)m * O_DIM + n0 + 4 * tx] =
            make_float4(o4[0], o4[1], o4[2], o4[3]);
    }
}

// ---------------------------------------------------------------------------
// Launch. Inputs: inputs[B,I], weights[O,I], biases[O], centers[O,I],
// inv_covars[O,I]. Output: [B,O] fp32.
// ---------------------------------------------------------------------------
extern "C" void kernel_launch(void* const* d_in, const int* in_sizes, int n_in,
                              void* d_out, int out_size)
{
    const float* X    = (const float*)d_in[0];
    const float* W    = (const float*)d_in[1];
    const float* bias = (const float*)d_in[2];
    const float* C    = (const float*)d_in[3];
    const float* V    = (const float*)d_in[4];

    const int O = in_sizes[2];               // 512
    const int I = in_sizes[1] / O;           // 512
    const int B = in_sizes[0] / I;           // 1024
    (void)n_in; (void)out_size;

    fgn_prep_kernel<<<O, 256>>>(C, V);

    dim3 grid(O / BN, B / BM);               // 8 x 16 = 128 CTAs
    fgn_main_kernel<<<grid, 256>>>(X, W, bias, (float*)d_out);
}